// round 15
// baseline (speedup 1.0000x reference)
#include <cuda_runtime.h>
#include <cstdint>

#define H      128
#define STEPS  65536
#define NC     8          // cluster = whole grid (portable size, proven)

__device__ __forceinline__ float tanh_fast(float x) {
    float y; asm("tanh.approx.f32 %0, %1;" : "=f"(y) : "f"(x)); return y;
}
__device__ __forceinline__ float sig_fast(float x) {
    return 0.5f * tanh_fast(0.5f * x) + 0.5f;
}
__device__ __forceinline__ float dot4(float4 a, float4 b) {
    return a.x * b.x + a.y * b.y + a.z * b.z + a.w * b.w;
}
__device__ __forceinline__ uint32_t smem_u32(const void* p) {
    uint32_t a;
    asm("{ .reg .u64 t; cvta.to.shared.u64 t, %1; cvt.u32.u64 %0, t; }"
        : "=r"(a) : "l"(p));
    return a;
}
__device__ __forceinline__ uint32_t mapa_u32(uint32_t a, uint32_t rank) {
    uint32_t r;
    asm("mapa.shared::cluster.u32 %0, %1, %2;" : "=r"(r) : "r"(a), "r"(rank));
    return r;
}
__device__ __forceinline__ void st_cluster_f32(uint32_t addr, float v) {
    asm volatile("st.shared::cluster.b32 [%0], %1;"
                 :: "r"(addr), "r"(__float_as_uint(v)) : "memory");
}
// release-ordered remote smem counter increment: makes this thread's prior
// remote data store visible to any acquire-observer of the counter.
__device__ __forceinline__ void red_rel_add(uint32_t addr, unsigned v) {
    asm volatile("red.release.cluster.shared::cluster.add.u32 [%0], %1;"
                 :: "r"(addr), "r"(v) : "memory");
}
__device__ __forceinline__ unsigned ld_acq_smem(uint32_t addr) {
    unsigned v;
    asm volatile("ld.acquire.cluster.shared::cta.u32 %0, [%1];"
                 : "=r"(v) : "r"(addr) : "memory");
    return v;
}
__device__ __forceinline__ void cluster_sync() {
    asm volatile("barrier.cluster.arrive.aligned;" ::: "memory");
    asm volatile("barrier.cluster.wait.aligned;"   ::: "memory");
}
__device__ __forceinline__ void mbar_init(uint32_t mb, uint32_t cnt) {
    asm volatile("mbarrier.init.shared.b64 [%0], %1;" :: "r"(mb), "r"(cnt) : "memory");
}
__device__ __forceinline__ void mbar_inval(uint32_t mb) {
    asm volatile("mbarrier.inval.shared.b64 [%0];" :: "r"(mb) : "memory");
}
__device__ __forceinline__ void mbar_expect_tx(uint32_t mb, uint32_t bytes) {
    asm volatile("mbarrier.arrive.expect_tx.shared.b64 _, [%0], %1;"
                 :: "r"(mb), "r"(bytes) : "memory");
}
__device__ __forceinline__ void tma_bulk_1d(uint32_t dst, const void* src,
                                            uint32_t bytes, uint32_t mb) {
    asm volatile(
        "cp.async.bulk.shared::cluster.global.mbarrier::complete_tx::bytes "
        "[%0], [%1], %2, [%3];"
        :: "r"(dst), "l"(src), "r"(bytes), "r"(mb) : "memory");
}
__device__ __forceinline__ void mbar_wait0(uint32_t mb) {
    asm volatile(
        "{\n\t.reg .pred P1;\n"
        "W%=:\n\t"
        "mbarrier.try_wait.parity.acquire.cta.shared::cta.b64 P1, [%0], 0, 0x989680;\n\t"
        "@P1 bra D%=;\n\t"
        "bra W%=;\n"
        "D%=:\n\t}"
        :: "r"(mb) : "memory");
}
// wait until the 4 stage counters (16B-aligned, local smem) sum to total.
// lane 0 polls with acquire loads; __syncwarp orders the rest of the warp.
__device__ __forceinline__ void wait_sum4(uint32_t base, unsigned total) {
    if ((threadIdx.x & 31) == 0) {
        unsigned s;
        do {
            s = ld_acq_smem(base) + ld_acq_smem(base + 4)
              + ld_acq_smem(base + 8) + ld_acq_smem(base + 12);
        } while (s < total);
    }
    __syncwarp();
}

// butterfly: ALL lanes end with the full sums
template <int N>
__device__ __forceinline__ void warp_bflyN(float* s) {
#pragma unroll
    for (int off = 16; off > 0; off >>= 1)
#pragma unroll
        for (int k = 0; k < N; ++k)
            s[k] += __shfl_xor_sync(0xFFFFFFFFu, s[k], off);
}

// Dynamic smem (floats): buf0[512] | buf1[512] | wl1[63 rows * 400]
#define OFF_BUF0  0
#define OFF_BUF1  512
#define OFF_WL1   1024
#define SMEM_FLOATS (1024 + 63 * 400)

extern __shared__ float sm[];

__global__ void __launch_bounds__(512, 1) __cluster_dims__(NC, 1, 1)
fused_rnn(const float* __restrict__ inputs,
          const float* __restrict__ W_ih,
          const float* __restrict__ b_ih,
          const float* __restrict__ b_hh,
          const float* __restrict__ W_fc,
          const float* __restrict__ b_fc,
          const float* __restrict__ W_l1,
          const float* __restrict__ b_l1,
          const float* __restrict__ W_l2,
          const float* __restrict__ b_l2,
          float* __restrict__ out)
{
    __shared__ __align__(8)  unsigned long long tma_mbar;
    __shared__ __align__(16) unsigned cnt[5][4];   // stage counters

    const int t    = threadIdx.x;
    const int wid  = t >> 5;
    const int lane = t & 31;
    uint32_t rank;
    asm("mov.u32 %0, %%cluster_ctarank;" : "=r"(rank));
    const int G  = (int)rank * 16 + wid;     // global warp id, 0..127
    const int fc = lane & 7;                 // FC fan-out target CTA
    const int fk = lane >> 3;                // FC fan-out row slot (0..3)

    float* buf0 = sm + OFF_BUF0;
    float* buf1 = sm + OFF_BUF1;
    float* wl1s = sm + OFF_WL1;

    // ---------- x0 first (critical path head) ----------
    if (t < 32)
        reinterpret_cast<float4*>(buf1)[t] =
            reinterpret_cast<const float4*>(inputs + (size_t)(STEPS - 1) * H)[t];

    // ---------- LSTM weights (regs): warp G owns the i, g, o rows of h[G] ----------
    float4 wl[3][3]; float bl[3][3];
#pragma unroll
    for (int l = 0; l < 3; ++l) {
        const int rows[3] = { G, 256 + G, 384 + G };
#pragma unroll
        for (int k = 0; k < 3; ++k) {
            wl[l][k] = reinterpret_cast<const float4*>(
                           W_ih + ((size_t)l * 512 + rows[k]) * H)[lane];
            bl[l][k] = b_ih[l * 512 + rows[k]] + b_hh[l * 512 + rows[k]];
        }
    }

    // ---------- FC weights (regs): rows G + 128k, k<4 (r<400) ----------
    float4 wfc[4]; float bfc[4];
#pragma unroll
    for (int k = 0; k < 4; ++k) {
        const int r = G + 128 * k;
        if (r < 400) {
            wfc[k] = reinterpret_cast<const float4*>(W_fc + (size_t)r * H)[lane];
            bfc[k] = b_fc[r];
        }
    }

    // ---------- L2 weights (regs): row G < 63 ----------
    float4 w2[4]; float b2 = 0.0f;
    if (G < 63) {
        const float4* wr = reinterpret_cast<const float4*>(W_l2 + (size_t)G * 500);
        w2[0] = wr[lane]; w2[1] = wr[lane + 32]; w2[2] = wr[lane + 64];
        if (lane < 29) w2[3] = wr[lane + 96];
        b2 = b_l2[G];
    }

    // ---------- L1: contiguous 63-row block per CTA via ONE TMA bulk ----------
    const int nrows = (rank == 7) ? 59 : 63;
    float bl1[4];
#pragma unroll
    for (int k = 0; k < 4; ++k) {
        const int l = wid + 16 * k;
        if (l < nrows) bl1[k] = b_l1[rank * 63 + l];
    }

    const uint32_t mb = smem_u32(&tma_mbar);
    if (t == 0) {
        // zero stage counters (ordered before any remote red by cluster_sync)
#pragma unroll
        for (int i = 0; i < 20; ++i) (&cnt[0][0])[i] = 0u;
        mbar_init(mb, 1);
        const uint32_t bytes = (uint32_t)nrows * 400u * 4u;
        mbar_expect_tx(mb, bytes);
        tma_bulk_1d(smem_u32(wl1s), W_l1 + (size_t)rank * 63 * 400, bytes, mb);
    }

    // one cluster rendezvous: counters zeroed + x0 staged, everywhere,
    // before any remote store/increment. Overlaps the in-flight weight LDGs.
    cluster_sync();

    // ================= LSTM layers: warp G produces finished h[G] =================
    // l=0: buf1 -> buf0; l=1: buf0 -> buf1; l=2: buf1 -> buf0
#pragma unroll
    for (int l = 0; l < 3; ++l) {
        float* xb = (l == 1) ? buf0 : buf1;
        float* hb = (l == 1) ? buf1 : buf0;

        const float4 x = reinterpret_cast<const float4*>(xb)[lane];
        float s[3];
#pragma unroll
        for (int k = 0; k < 3; ++k) s[k] = dot4(wl[l][k], x);
        warp_bflyN<3>(s);

        const float c = sig_fast(s[0] + bl[l][0]) * tanh_fast(s[1] + bl[l][1]);
        const float h = sig_fast(s[2] + bl[l][2]) * tanh_fast(c);
        if (lane < 8) {                         // fan h + count to all CTAs
            st_cluster_f32(mapa_u32(smem_u32(&hb[G]), lane), h);
            red_rel_add(mapa_u32(smem_u32(&cnt[l][G >> 5]), lane), 1u);
        }
        wait_sum4(smem_u32(&cnt[l][0]), 128u);  // all 128 h values landed
    }

    // ================= FC 400x128: buf0 -> buf1 =================
    {
        const float4 x = reinterpret_cast<const float4*>(buf0)[lane];
        float s[4];
#pragma unroll
        for (int k = 0; k < 4; ++k)
            s[k] = (G + 128 * k < 400) ? dot4(wfc[k], x) : 0.0f;
        warp_bflyN<4>(s);

        const int r = G + 128 * fk;             // 32 lanes = 4 rows x 8 CTAs
        if (r < 400) {
            float v = s[0] + bfc[0];
#pragma unroll
            for (int k = 1; k < 4; ++k)
                if (fk == k) v = s[k] + bfc[k];
            st_cluster_f32(mapa_u32(smem_u32(&buf1[r]), fc), v);
            red_rel_add(mapa_u32(smem_u32(&cnt[3][fk]), fc), 1u);
        }
        wait_sum4(smem_u32(&cnt[3][0]), 400u);
    }

    // ================= L1 500x400: buf1 -> buf0 (only ranks 0-3 receive) =========
    {
        mbar_wait0(mb);                         // TMA complete + acquire

        const float4* xf = reinterpret_cast<const float4*>(buf1);
        const float4 x0 = xf[lane], x1 = xf[lane + 32], x2 = xf[lane + 64];
        float4 x3 = make_float4(0.f, 0.f, 0.f, 0.f);
        if (lane < 4) x3 = xf[lane + 96];

        float s[4];
#pragma unroll
        for (int k = 0; k < 4; ++k) {
            float v = 0.0f;
            const int l = wid + 16 * k;
            if (l < nrows) {
                const float4* wr = reinterpret_cast<const float4*>(wl1s + l * 400);
                v = dot4(wr[lane], x0) + dot4(wr[lane + 32], x1)
                  + dot4(wr[lane + 64], x2);
                if (lane < 4) v += dot4(wr[lane + 96], x3);
            }
            s[k] = v;
        }
        warp_bflyN<4>(s);

        // fan only to ranks 0-3 (the L2 producers): 16 lanes = 4 rows x 4 CTAs
        if (lane < 16) {
            const int tgt  = lane & 3;
            const int slot = lane >> 2;
            const int l = wid + 16 * slot;
            if (l < nrows) {
                float v = s[0] + bl1[0];
#pragma unroll
                for (int k = 1; k < 4; ++k)
                    if (slot == k) v = s[k] + bl1[k];
                st_cluster_f32(mapa_u32(smem_u32(&buf0[rank * 63 + l]), tgt), v);
                red_rel_add(mapa_u32(smem_u32(&cnt[4][slot]), tgt), 1u);
            }
        }
    }

    // ================= L2 63x500: ranks 0-3, buf0 -> gmem =================
    if (rank < 4) {
        wait_sum4(smem_u32(&cnt[4][0]), 500u);
        if (G < 63) {
            const float4* xf = reinterpret_cast<const float4*>(buf0);
            float s[1];
            s[0] = dot4(w2[0], xf[lane]) + dot4(w2[1], xf[lane + 32])
                 + dot4(w2[2], xf[lane + 64]);
            if (lane < 29) s[0] += dot4(w2[3], xf[lane + 96]);
            warp_bflyN<1>(s);
            if (lane == 0) out[G] = s[0] + b2;
        }
    }

    // hygiene for graph replays: mbar back to invalid (counters re-zeroed at start)
    __syncthreads();
    if (t == 0) mbar_inval(mb);
}

extern "C" void kernel_launch(void* const* d_in, const int* in_sizes, int n_in,
                              void* d_out, int out_size) {
    const float* inputs = (const float*)d_in[0];
    const float* W_ih   = (const float*)d_in[1];
    // d_in[2] = W_hh — dead (h0 = 0)
    const float* b_ih   = (const float*)d_in[3];
    const float* b_hh   = (const float*)d_in[4];
    const float* W_fc   = (const float*)d_in[5];
    const float* b_fc   = (const float*)d_in[6];
    const float* W_l1   = (const float*)d_in[7];
    const float* b_l1   = (const float*)d_in[8];
    const float* W_l2   = (const float*)d_in[9];
    const float* b_l2   = (const float*)d_in[10];
    float* out = (float*)d_out;

    const int dynSmem = SMEM_FLOATS * 4;     // ~103 KB
    cudaFuncSetAttribute(fused_rnn,
                         cudaFuncAttributeMaxDynamicSharedMemorySize, dynSmem);

    fused_rnn<<<NC, 512, dynSmem>>>(inputs, W_ih, b_ih, b_hh,
                                    W_fc, b_fc, W_l1, b_l1, W_l2, b_l2, out);
}

// round 16
// speedup vs baseline: 1.8246x; 1.8246x over previous
#include <cuda_runtime.h>
#include <cstdint>

#define H      128
#define STEPS  65536
#define NC     8          // cluster = whole grid (portable size, proven)

__device__ __forceinline__ float tanh_fast(float x) {
    float y; asm("tanh.approx.f32 %0, %1;" : "=f"(y) : "f"(x)); return y;
}
__device__ __forceinline__ float sig_fast(float x) {
    return 0.5f * tanh_fast(0.5f * x) + 0.5f;
}
__device__ __forceinline__ float dot4(float4 a, float4 b) {
    return a.x * b.x + a.y * b.y + a.z * b.z + a.w * b.w;
}
__device__ __forceinline__ uint32_t smem_u32(const void* p) {
    uint32_t a;
    asm("{ .reg .u64 t; cvta.to.shared.u64 t, %1; cvt.u32.u64 %0, t; }"
        : "=r"(a) : "l"(p));
    return a;
}
__device__ __forceinline__ uint32_t mapa_u32(uint32_t a, uint32_t rank) {
    uint32_t r;
    asm("mapa.shared::cluster.u32 %0, %1, %2;" : "=r"(r) : "r"(a), "r"(rank));
    return r;
}
__device__ __forceinline__ void st_cluster_f32(uint32_t addr, float v) {
    asm volatile("st.shared::cluster.b32 [%0], %1;"
                 :: "r"(addr), "r"(__float_as_uint(v)) : "memory");
}
__device__ __forceinline__ void cluster_sync() {
    asm volatile("barrier.cluster.arrive.aligned;" ::: "memory");
    asm volatile("barrier.cluster.wait.aligned;"   ::: "memory");
}
__device__ __forceinline__ void mbar_init(uint32_t mb, uint32_t cnt) {
    asm volatile("mbarrier.init.shared.b64 [%0], %1;" :: "r"(mb), "r"(cnt) : "memory");
}
__device__ __forceinline__ void mbar_inval(uint32_t mb) {
    asm volatile("mbarrier.inval.shared.b64 [%0];" :: "r"(mb) : "memory");
}
__device__ __forceinline__ void mbar_expect_tx(uint32_t mb, uint32_t bytes) {
    asm volatile("mbarrier.arrive.expect_tx.shared.b64 _, [%0], %1;"
                 :: "r"(mb), "r"(bytes) : "memory");
}
// 1D bulk copy gmem -> local smem, completion -> mbar (no tensormap needed)
__device__ __forceinline__ void tma_bulk_1d(uint32_t dst, const void* src,
                                            uint32_t bytes, uint32_t mb) {
    asm volatile(
        "cp.async.bulk.shared::cluster.global.mbarrier::complete_tx::bytes "
        "[%0], [%1], %2, [%3];"
        :: "r"(dst), "l"(src), "r"(bytes), "r"(mb) : "memory");
}
__device__ __forceinline__ void mbar_wait0(uint32_t mb) {
    asm volatile(
        "{\n\t.reg .pred P1;\n"
        "W%=:\n\t"
        "mbarrier.try_wait.parity.acquire.cta.shared::cta.b64 P1, [%0], 0, 0x989680;\n\t"
        "@P1 bra D%=;\n\t"
        "bra W%=;\n"
        "D%=:\n\t}"
        :: "r"(mb) : "memory");
}

// butterfly: ALL lanes end with the full sums
template <int N>
__device__ __forceinline__ void warp_bflyN(float* s) {
#pragma unroll
    for (int off = 16; off > 0; off >>= 1)
#pragma unroll
        for (int k = 0; k < N; ++k)
            s[k] += __shfl_xor_sync(0xFFFFFFFFu, s[k], off);
}

// Dynamic smem (floats): buf0[512] | buf1[512] | wl1[63 rows * 400]
#define OFF_BUF0  0
#define OFF_BUF1  512
#define OFF_WL1   1024
#define SMEM_FLOATS (1024 + 63 * 400)

extern __shared__ float sm[];

__global__ void __launch_bounds__(512, 1) __cluster_dims__(NC, 1, 1)
fused_rnn(const float* __restrict__ inputs,
          const float* __restrict__ W_ih,
          const float* __restrict__ b_ih,
          const float* __restrict__ b_hh,
          const float* __restrict__ W_fc,
          const float* __restrict__ b_fc,
          const float* __restrict__ W_l1,
          const float* __restrict__ b_l1,
          const float* __restrict__ W_l2,
          const float* __restrict__ b_l2,
          float* __restrict__ out)
{
    __shared__ __align__(8) unsigned long long tma_mbar;

    const int t    = threadIdx.x;
    const int wid  = t >> 5;
    const int lane = t & 31;
    uint32_t rank;
    asm("mov.u32 %0, %%cluster_ctarank;" : "=r"(rank));
    const int G  = (int)rank * 16 + wid;     // global warp id, 0..127
    const int fc = lane & 7;                 // FC fan-out target CTA
    const int fk = lane >> 3;                // FC fan-out row slot (0..3)

    float* buf0 = sm + OFF_BUF0;
    float* buf1 = sm + OFF_BUF1;
    float* wl1s = sm + OFF_WL1;

    // ---------- TMA for W_l1 issued FIRST (off the LSU path, max overlap) ----------
    // CTA rank owns rows [rank*63, rank*63 + nrows), nrows = 63 (rank 7: 59).
    const int nrows = (rank == 7) ? 59 : 63;
    const uint32_t mb = smem_u32(&tma_mbar);
    if (t == 0) {
        mbar_init(mb, 1);
        const uint32_t bytes = (uint32_t)nrows * 400u * 4u;
        mbar_expect_tx(mb, bytes);
        tma_bulk_1d(smem_u32(wl1s), W_l1 + (size_t)rank * 63 * 400, bytes, mb);
    }
    // (other threads touch mb only at mbar_wait0, ordered by the cluster_syncs)

    // ---------- x0: last-timestep input ----------
    if (t < 32)
        reinterpret_cast<float4*>(buf1)[t] =
            reinterpret_cast<const float4*>(inputs + (size_t)(STEPS - 1) * H)[t];

    // ---------- LSTM weights (regs): warp G owns the i, g, o rows of h[G] ----------
    // PyTorch gate order i,f,g,o -> rows G, 256+G, 384+G (f dead: c0=0).
    float4 wl[3][3]; float bl[3][3];
#pragma unroll
    for (int l = 0; l < 3; ++l) {
        const int rows[3] = { G, 256 + G, 384 + G };
#pragma unroll
        for (int k = 0; k < 3; ++k) {
            wl[l][k] = reinterpret_cast<const float4*>(
                           W_ih + ((size_t)l * 512 + rows[k]) * H)[lane];
            bl[l][k] = b_ih[l * 512 + rows[k]] + b_hh[l * 512 + rows[k]];
        }
    }

    // ---------- FC weights (regs): rows G + 128k, k<4 (r<400) ----------
    float4 wfc[4]; float bfc[4];
#pragma unroll
    for (int k = 0; k < 4; ++k) {
        const int r = G + 128 * k;
        if (r < 400) {
            wfc[k] = reinterpret_cast<const float4*>(W_fc + (size_t)r * H)[lane];
            bfc[k] = b_fc[r];
        }
    }

    // ---------- L2 weights (regs): row G < 63 ----------
    float4 w2[4]; float b2 = 0.0f;
    if (G < 63) {
        const float4* wr = reinterpret_cast<const float4*>(W_l2 + (size_t)G * 500);
        w2[0] = wr[lane]; w2[1] = wr[lane + 32]; w2[2] = wr[lane + 64];
        if (lane < 29) w2[3] = wr[lane + 96];
        b2 = b_l2[G];
    }

    // ---------- L1 biases ----------
    float bl1[4];
#pragma unroll
    for (int k = 0; k < 4; ++k) {
        const int l = wid + 16 * k;
        if (l < nrows) bl1[k] = b_l1[rank * 63 + l];
    }

    __syncthreads();   // x0 + mbar init visible CTA-wide

    // ================= LSTM layers: warp G produces finished h[G] =================
    // l=0: buf1 -> buf0; l=1: buf0 -> buf1; l=2: buf1 -> buf0
#pragma unroll
    for (int l = 0; l < 3; ++l) {
        float* xb = (l == 1) ? buf0 : buf1;
        float* hb = (l == 1) ? buf1 : buf0;

        const float4 x = reinterpret_cast<const float4*>(xb)[lane];
        float s[3];
#pragma unroll
        for (int k = 0; k < 3; ++k) s[k] = dot4(wl[l][k], x);
        warp_bflyN<3>(s);                      // all lanes: i,g,o sums

        const float c = sig_fast(s[0] + bl[l][0]) * tanh_fast(s[1] + bl[l][1]);
        const float h = sig_fast(s[2] + bl[l][2]) * tanh_fast(c);
        if (lane < 8)                           // fan finished h to all CTAs
            st_cluster_f32(mapa_u32(smem_u32(&hb[G]), lane), h);

        cluster_sync();                         // release stores / acquire reads
    }

    // ================= FC 400x128: buf0 -> buf1 =================
    {
        const float4 x = reinterpret_cast<const float4*>(buf0)[lane];
        float s[4];
#pragma unroll
        for (int k = 0; k < 4; ++k)
            s[k] = (G + 128 * k < 400) ? dot4(wfc[k], x) : 0.0f;
        warp_bflyN<4>(s);

        const int r = G + 128 * fk;             // 32 lanes = 4 rows x 8 CTAs
        if (r < 400) {
            float v = s[0] + bfc[0];
#pragma unroll
            for (int k = 1; k < 4; ++k)
                if (fk == k) v = s[k] + bfc[k];
            st_cluster_f32(mapa_u32(smem_u32(&buf1[r]), fc), v);
        }
        cluster_sync();
    }

    // ================= L1 500x400: buf1 -> buf0 (fan only to ranks 0-3) ==========
    {
        mbar_wait0(mb);                         // TMA complete + acquire

        const float4* xf = reinterpret_cast<const float4*>(buf1);
        const float4 x0 = xf[lane], x1 = xf[lane + 32], x2 = xf[lane + 64];
        float4 x3 = make_float4(0.f, 0.f, 0.f, 0.f);
        if (lane < 4) x3 = xf[lane + 96];

        float s[4];
#pragma unroll
        for (int k = 0; k < 4; ++k) {
            float v = 0.0f;
            const int l = wid + 16 * k;
            if (l < nrows) {
                const float4* wr = reinterpret_cast<const float4*>(wl1s + l * 400);
                v = dot4(wr[lane], x0) + dot4(wr[lane + 32], x1)
                  + dot4(wr[lane + 64], x2);
                if (lane < 4) v += dot4(wr[lane + 96], x3);
            }
            s[k] = v;
        }
        warp_bflyN<4>(s);

        // 16 lanes = 4 row-slots x 4 target CTAs (ranks 0-3, the L2 producers)
        if (lane < 16) {
            const int tgt  = lane & 3;
            const int slot = lane >> 2;
            const int l = wid + 16 * slot;
            if (l < nrows) {
                float v = s[0] + bl1[0];
#pragma unroll
                for (int k = 1; k < 4; ++k)
                    if (slot == k) v = s[k] + bl1[k];
                st_cluster_f32(mapa_u32(smem_u32(&buf0[rank * 63 + l]), tgt), v);
            }
        }
        cluster_sync();
    }

    // ================= L2 63x500: ranks 0-3, buf0 -> gmem =================
    if (G < 63) {
        const float4* xf = reinterpret_cast<const float4*>(buf0);
        float s[1];
        s[0] = dot4(w2[0], xf[lane]) + dot4(w2[1], xf[lane + 32])
             + dot4(w2[2], xf[lane + 64]);
        if (lane < 29) s[0] += dot4(w2[3], xf[lane + 96]);
        warp_bflyN<1>(s);
        if (lane == 0) out[G] = s[0] + b2;
    }

    // hygiene for graph replays: inval so next launch's init is clean.
    __syncthreads();
    if (t == 0) mbar_inval(mb);
}

extern "C" void kernel_launch(void* const* d_in, const int* in_sizes, int n_in,
                              void* d_out, int out_size) {
    const float* inputs = (const float*)d_in[0];
    const float* W_ih   = (const float*)d_in[1];
    // d_in[2] = W_hh — dead (h0 = 0)
    const float* b_ih   = (const float*)d_in[3];
    const float* b_hh   = (const float*)d_in[4];
    const float* W_fc   = (const float*)d_in[5];
    const float* b_fc   = (const float*)d_in[6];
    const float* W_l1   = (const float*)d_in[7];
    const float* b_l1   = (const float*)d_in[8];
    const float* W_l2   = (const float*)d_in[9];
    const float* b_l2   = (const float*)d_in[10];
    float* out = (float*)d_out;

    const int dynSmem = SMEM_FLOATS * 4;     // ~103 KB
    cudaFuncSetAttribute(fused_rnn,
                         cudaFuncAttributeMaxDynamicSharedMemorySize, dynSmem);

    fused_rnn<<<NC, 512, dynSmem>>>(inputs, W_ih, b_ih, b_hh,
                                    W_fc, b_fc, W_l1, b_l1, W_l2, b_l2, out);
}

// round 17
// speedup vs baseline: 2.1224x; 1.1633x over previous
#include <cuda_runtime.h>
#include <cstdint>

#define H      128
#define STEPS  65536
#define NC     8          // cluster = whole grid (portable size, proven)

__device__ __forceinline__ float tanh_fast(float x) {
    float y; asm("tanh.approx.f32 %0, %1;" : "=f"(y) : "f"(x)); return y;
}
__device__ __forceinline__ float sig_fast(float x) {
    return 0.5f * tanh_fast(0.5f * x) + 0.5f;
}
__device__ __forceinline__ float dot4(float4 a, float4 b) {
    return a.x * b.x + a.y * b.y + a.z * b.z + a.w * b.w;
}
__device__ __forceinline__ uint32_t smem_u32(const void* p) {
    uint32_t a;
    asm("{ .reg .u64 t; cvta.to.shared.u64 t, %1; cvt.u32.u64 %0, t; }"
        : "=r"(a) : "l"(p));
    return a;
}
__device__ __forceinline__ uint32_t mapa_u32(uint32_t a, uint32_t rank) {
    uint32_t r;
    asm("mapa.shared::cluster.u32 %0, %1, %2;" : "=r"(r) : "r"(a), "r"(rank));
    return r;
}
__device__ __forceinline__ void cluster_sync() {
    asm volatile("barrier.cluster.arrive.aligned;" ::: "memory");
    asm volatile("barrier.cluster.wait.aligned;"   ::: "memory");
}
__device__ __forceinline__ void mbar_init(uint32_t mb, uint32_t cnt) {
    asm volatile("mbarrier.init.shared.b64 [%0], %1;" :: "r"(mb), "r"(cnt) : "memory");
}
__device__ __forceinline__ void mbar_inval(uint32_t mb) {
    asm volatile("mbarrier.inval.shared.b64 [%0];" :: "r"(mb) : "memory");
}
__device__ __forceinline__ void mbar_expect_tx(uint32_t mb, uint32_t bytes) {
    asm volatile("mbarrier.arrive.expect_tx.shared.b64 _, [%0], %1;"
                 :: "r"(mb), "r"(bytes) : "memory");
}
// global -> local smem bulk (TMA engine), completion -> local mbar
__device__ __forceinline__ void tma_bulk_g2s(uint32_t dst, const void* src,
                                             uint32_t bytes, uint32_t mb) {
    asm volatile(
        "cp.async.bulk.shared::cluster.global.mbarrier::complete_tx::bytes "
        "[%0], [%1], %2, [%3];"
        :: "r"(dst), "l"(src), "r"(bytes), "r"(mb) : "memory");
}
// local smem -> remote CTA smem bulk, completion tx -> REMOTE CTA's mbar
__device__ __forceinline__ void dsmem_bulk_s2s(uint32_t dst_cluster,
                                               uint32_t src_local,
                                               uint32_t bytes,
                                               uint32_t mbar_cluster) {
    asm volatile(
        "cp.async.bulk.shared::cluster.shared::cta.mbarrier::complete_tx::bytes "
        "[%0], [%1], %2, [%3];"
        :: "r"(dst_cluster), "r"(src_local), "r"(bytes), "r"(mbar_cluster)
        : "memory");
}
__device__ __forceinline__ void fence_proxy_async_smem() {
    asm volatile("fence.proxy.async.shared::cta;" ::: "memory");
}
__device__ __forceinline__ void bulk_commit() {
    asm volatile("cp.async.bulk.commit_group;" ::: "memory");
}
__device__ __forceinline__ void bulk_wait_read0() {
    asm volatile("cp.async.bulk.wait_group.read 0;" ::: "memory");
}
__device__ __forceinline__ void mbar_wait0(uint32_t mb) {
    asm volatile(
        "{\n\t.reg .pred P1;\n"
        "W%=:\n\t"
        "mbarrier.try_wait.parity.acquire.cta.shared::cta.b64 P1, [%0], 0, 0x989680;\n\t"
        "@P1 bra D%=;\n\t"
        "bra W%=;\n"
        "D%=:\n\t}"
        :: "r"(mb) : "memory");
}

// butterfly: ALL lanes end with the full sums
template <int N>
__device__ __forceinline__ void warp_bflyN(float* s) {
#pragma unroll
    for (int off = 16; off > 0; off >>= 1)
#pragma unroll
        for (int k = 0; k < N; ++k)
            s[k] += __shfl_xor_sync(0xFFFFFFFFu, s[k], off);
}

// Dynamic smem (floats): buf0[512] | buf1[512] | wl1[64 rows * 400]
#define OFF_BUF0  0
#define OFF_BUF1  512
#define OFF_WL1   1024
#define SMEM_FLOATS (1024 + 64 * 400)

extern __shared__ float sm[];

__global__ void __launch_bounds__(512, 1) __cluster_dims__(NC, 1, 1)
fused_rnn(const float* __restrict__ inputs,
          const float* __restrict__ W_ih,
          const float* __restrict__ b_ih,
          const float* __restrict__ b_hh,
          const float* __restrict__ W_fc,
          const float* __restrict__ b_fc,
          const float* __restrict__ W_l1,
          const float* __restrict__ b_l1,
          const float* __restrict__ W_l2,
          const float* __restrict__ b_l2,
          float* __restrict__ out)
{
    // mbars: 0,1,2 = LSTM hops; 3 = FC; 4 = L1; 5 = W_l1 TMA
    __shared__ __align__(8)  unsigned long long mbars[6];
    // stage buffers (distinct per hop; bulk sources must stay intact)
    __shared__ __align__(16) float stg_l[3][16];
    __shared__ __align__(16) float stg_fc[52];
    __shared__ __align__(16) float stg_l1[64];

    const int t    = threadIdx.x;
    const int wid  = t >> 5;
    const int lane = t & 31;
    uint32_t rank;
    asm("mov.u32 %0, %%cluster_ctarank;" : "=r"(rank));
    const int G = (int)rank * 16 + wid;      // global warp id, 0..127

    float* buf0 = sm + OFF_BUF0;
    float* buf1 = sm + OFF_BUF1;
    float* wl1s = sm + OFF_WL1;

    // per-CTA row blocks (all 16B-multiple transfers)
    const int nfc = (rank == 7) ? 36 : 52;   // FC rows: [52*rank, +nfc)
    const int nl1 = (rank == 7) ? 52 : 64;   // L1 rows: [64*rank, +nl1)

    // ---------- init mbars + post expects + launch W_l1 TMA (thread 0) ----------
    if (t == 0) {
#pragma unroll
        for (int i = 0; i < 6; ++i) mbar_init(smem_u32(&mbars[i]), 1);
        mbar_expect_tx(smem_u32(&mbars[0]), 512u);    // 8 x 64B h-blocks
        mbar_expect_tx(smem_u32(&mbars[1]), 512u);
        mbar_expect_tx(smem_u32(&mbars[2]), 512u);
        mbar_expect_tx(smem_u32(&mbars[3]), 1600u);   // 400 floats
        mbar_expect_tx(smem_u32(&mbars[4]), 2000u);   // 500 floats (ranks 0-3)
        const uint32_t bytes = (uint32_t)nl1 * 400u * 4u;
        mbar_expect_tx(smem_u32(&mbars[5]), bytes);
        tma_bulk_g2s(smem_u32(wl1s), W_l1 + (size_t)rank * 64 * 400,
                     bytes, smem_u32(&mbars[5]));
    }

    // ---------- x0: last-timestep input ----------
    if (t < 32)
        reinterpret_cast<float4*>(buf1)[t] =
            reinterpret_cast<const float4*>(inputs + (size_t)(STEPS - 1) * H)[t];

    // ---------- LSTM weights (regs): warp G owns i, g, o rows of h[G] ----------
    float4 wl[3][3]; float bl[3][3];
#pragma unroll
    for (int l = 0; l < 3; ++l) {
        const int rows[3] = { G, 256 + G, 384 + G };   // f dead (c0=0)
#pragma unroll
        for (int k = 0; k < 3; ++k) {
            wl[l][k] = reinterpret_cast<const float4*>(
                           W_ih + ((size_t)l * 512 + rows[k]) * H)[lane];
            bl[l][k] = b_ih[l * 512 + rows[k]] + b_hh[l * 512 + rows[k]];
        }
    }

    // ---------- FC weights (regs): rows 52*rank + wid + 16k ----------
    float4 wfc[4]; float bfc[4];
#pragma unroll
    for (int k = 0; k < 4; ++k) {
        const int lr = wid + 16 * k;
        if (lr < nfc) {
            const int r = 52 * (int)rank + lr;
            wfc[k] = reinterpret_cast<const float4*>(W_fc + (size_t)r * H)[lane];
            bfc[k] = b_fc[r];
        }
    }

    // ---------- L2 weights (regs): row G < 63 ----------
    float4 w2[4]; float b2 = 0.0f;
    if (G < 63) {
        const float4* wr = reinterpret_cast<const float4*>(W_l2 + (size_t)G * 500);
        w2[0] = wr[lane]; w2[1] = wr[lane + 32]; w2[2] = wr[lane + 64];
        if (lane < 29) w2[3] = wr[lane + 96];
        b2 = b_l2[G];
    }

    // ---------- L1 biases ----------
    float bl1[4];
#pragma unroll
    for (int k = 0; k < 4; ++k) {
        const int lr = wid + 16 * k;
        if (lr < nl1) bl1[k] = b_l1[64 * (int)rank + lr];
    }

    // one rendezvous: mbar inits + expects + x0 visible cluster-wide before
    // any remote bulk can land. Overlaps the in-flight weight LDGs.
    cluster_sync();

    // ================= LSTM layers: warp G produces finished h[G] =================
    // l=0: buf1 -> buf0; l=1: buf0 -> buf1; l=2: buf1 -> buf0
#pragma unroll
    for (int l = 0; l < 3; ++l) {
        float* xb = (l == 1) ? buf0 : buf1;
        float* hb = (l == 1) ? buf1 : buf0;

        const float4 x = reinterpret_cast<const float4*>(xb)[lane];
        float s[3];
#pragma unroll
        for (int k = 0; k < 3; ++k) s[k] = dot4(wl[l][k], x);
        warp_bflyN<3>(s);

        const float c = sig_fast(s[0] + bl[l][0]) * tanh_fast(s[1] + bl[l][1]);
        const float h = sig_fast(s[2] + bl[l][2]) * tanh_fast(c);
        if (lane == 0) stg_l[l][wid] = h;        // local stage (16 floats)
        __syncthreads();

        if (t == 0) {                             // one 64B bulk per target CTA
            fence_proxy_async_smem();
            const uint32_t src = smem_u32(&stg_l[l][0]);
            const uint32_t dst = smem_u32(&hb[rank * 16]);
            const uint32_t mbh = smem_u32(&mbars[l]);
#pragma unroll
            for (int tgt = 0; tgt < NC; ++tgt)
                dsmem_bulk_s2s(mapa_u32(dst, tgt), src, 64u, mapa_u32(mbh, tgt));
        }
        mbar_wait0(smem_u32(&mbars[l]));          // all 8 blocks landed here
    }

    // ================= FC 400x128: buf0 -> buf1 =================
    {
        const float4 x = reinterpret_cast<const float4*>(buf0)[lane];
        float s[4];
#pragma unroll
        for (int k = 0; k < 4; ++k)
            s[k] = (wid + 16 * k < nfc) ? dot4(wfc[k], x) : 0.0f;
        warp_bflyN<4>(s);

        if (lane == 0) {
#pragma unroll
            for (int k = 0; k < 4; ++k) {
                const int lr = wid + 16 * k;
                if (lr < nfc) stg_fc[lr] = s[k] + bfc[k];
            }
        }
        __syncthreads();

        if (t == 0) {
            fence_proxy_async_smem();
            const uint32_t src = smem_u32(&stg_fc[0]);
            const uint32_t dst = smem_u32(&buf1[52 * rank]);
            const uint32_t mbh = smem_u32(&mbars[3]);
            const uint32_t bytes = (uint32_t)nfc * 4u;   // 208 / 144
#pragma unroll
            for (int tgt = 0; tgt < NC; ++tgt)
                dsmem_bulk_s2s(mapa_u32(dst, tgt), src, bytes, mapa_u32(mbh, tgt));
        }
        mbar_wait0(smem_u32(&mbars[3]));
    }

    // ================= L1 500x400: buf1 -> buf0 (fan to ranks 0-3) =================
    {
        mbar_wait0(smem_u32(&mbars[5]));          // W_l1 TMA complete

        const float4* xf = reinterpret_cast<const float4*>(buf1);
        const float4 x0 = xf[lane], x1 = xf[lane + 32], x2 = xf[lane + 64];
        float4 x3 = make_float4(0.f, 0.f, 0.f, 0.f);
        if (lane < 4) x3 = xf[lane + 96];

        float s[4];
#pragma unroll
        for (int k = 0; k < 4; ++k) {
            float v = 0.0f;
            const int lr = wid + 16 * k;
            if (lr < nl1) {
                const float4* wr = reinterpret_cast<const float4*>(wl1s + lr * 400);
                v = dot4(wr[lane], x0) + dot4(wr[lane + 32], x1)
                  + dot4(wr[lane + 64], x2);
                if (lane < 4) v += dot4(wr[lane + 96], x3);
            }
            s[k] = v;
        }
        warp_bflyN<4>(s);

        if (lane == 0) {
#pragma unroll
            for (int k = 0; k < 4; ++k) {
                const int lr = wid + 16 * k;
                if (lr < nl1) stg_l1[lr] = s[k] + bl1[k];
            }
        }
        __syncthreads();

        if (t == 0) {
            fence_proxy_async_smem();
            const uint32_t src = smem_u32(&stg_l1[0]);
            const uint32_t dst = smem_u32(&buf0[64 * rank]);
            const uint32_t mbh = smem_u32(&mbars[4]);
            const uint32_t bytes = (uint32_t)nl1 * 4u;   // 256 / 208
#pragma unroll
            for (int tgt = 0; tgt < 4; ++tgt)             // L2 producers only
                dsmem_bulk_s2s(mapa_u32(dst, tgt), src, bytes, mapa_u32(mbh, tgt));
        }
    }

    // ================= L2 63x500: ranks 0-3, buf0 -> gmem =================
    if (rank < 4) {
        mbar_wait0(smem_u32(&mbars[4]));
        if (G < 63) {
            const float4* xf = reinterpret_cast<const float4*>(buf0);
            float s[1];
            s[0] = dot4(w2[0], xf[lane]) + dot4(w2[1], xf[lane + 32])
                 + dot4(w2[2], xf[lane + 64]);
            if (lane < 29) s[0] += dot4(w2[3], xf[lane + 96]);
            warp_bflyN<1>(s);
            if (lane == 0) out[G] = s[0] + b2;
        }
    }

    // exit safety + replay hygiene: source reads of all issued bulks must be
    // complete before this CTA exits; then invalidate mbars for next replay.
    __syncthreads();
    if (t == 0) {
        bulk_commit();
        bulk_wait_read0();
#pragma unroll
        for (int i = 0; i < 6; ++i) mbar_inval(smem_u32(&mbars[i]));
    }
}

extern "C" void kernel_launch(void* const* d_in, const int* in_sizes, int n_in,
                              void* d_out, int out_size) {
    const float* inputs = (const float*)d_in[0];
    const float* W_ih   = (const float*)d_in[1];
    // d_in[2] = W_hh — dead (h0 = 0)
    const float* b_ih   = (const float*)d_in[3];
    const float* b_hh   = (const float*)d_in[4];
    const float* W_fc   = (const float*)d_in[5];
    const float* b_fc   = (const float*)d_in[6];
    const float* W_l1   = (const float*)d_in[7];
    const float* b_l1   = (const float*)d_in[8];
    const float* W_l2   = (const float*)d_in[9];
    const float* b_l2   = (const float*)d_in[10];
    float* out = (float*)d_out;

    const int dynSmem = SMEM_FLOATS * 4;     // ~104 KB
    cudaFuncSetAttribute(fused_rnn,
                         cudaFuncAttributeMaxDynamicSharedMemorySize, dynSmem);

    fused_rnn<<<NC, 512, dynSmem>>>(inputs, W_ih, b_ih, b_hh,
                                    W_fc, b_fc, W_l1, b_l1, W_l2, b_l2, out);
}